// round 7
// baseline (speedup 1.0000x reference)
#include <cuda_runtime.h>
#include <cstdint>

#define H        256
#define NG       2048
#define APG      64
#define GRID     148
#define TILE_F   (APG*H)       // 16384 floats
#define TILE_B   (TILE_F*4)    // 65536 bytes
#define GMAX     14
#define NTHR     640           // 12 attention warps + 8 matvec warps
#define ATT_THR  384

// ---------------- device globals ----------------
__device__ float4 g_WcT4[64 * 1024];   // [kc][n] = (W_ih+W_hh)[n][4kc..4kc+3]
__device__ float  g_bc[1024];
__device__ float  g_q0[H];
__device__ float  g_c0[H];

__device__ __forceinline__ float sigmoidf_(float v) {
    return 1.0f / (1.0f + __expf(-v));
}

// ---------------- prep ----------------
__global__ void prep_kernel(const float* __restrict__ W_ih,
                            const float* __restrict__ W_hh,
                            const float* __restrict__ b_ih,
                            const float* __restrict__ b_hh) {
    int idx = blockIdx.x * 256 + threadIdx.x;    // 65536 threads
    int kc = idx >> 10, n = idx & 1023;
    float4 a = *(const float4*)&W_ih[n * H + kc * 4];
    float4 b = *(const float4*)&W_hh[n * H + kc * 4];
    g_WcT4[idx] = make_float4(a.x + b.x, a.y + b.y, a.z + b.z, a.w + b.w);
    if (idx < 1024) g_bc[idx] = b_ih[idx] + b_hh[idx];
    if (idx < H) {
        float gi = b_ih[idx]       + b_hh[idx];
        float gg = b_ih[512 + idx] + b_hh[512 + idx];
        float go = b_ih[768 + idx] + b_hh[768 + idx];
        float c  = sigmoidf_(gi) * tanhf(gg);
        g_c0[idx] = c;
        g_q0[idx] = sigmoidf_(go) * tanhf(c);
    }
}

// ---------------- packed f32x2 helpers ----------------
__device__ __forceinline__ unsigned long long pack2(float lo, float hi) {
    unsigned long long r;
    asm("mov.b64 %0, {%1, %2};" : "=l"(r) : "f"(lo), "f"(hi));
    return r;
}
__device__ __forceinline__ void ffma2(unsigned long long& d,
                                      unsigned long long a,
                                      unsigned long long b) {
    asm("fma.rn.f32x2 %0, %1, %2, %0;" : "+l"(d) : "l"(a), "l"(b));
}
__device__ __forceinline__ float2 unpack2(unsigned long long v) {
    union { unsigned long long u; float2 f; } cv; cv.u = v; return cv.f;
}

// named barrier helpers
__device__ __forceinline__ void nbar_sync(int id, int cnt) {
    asm volatile("bar.sync %0, %1;" :: "r"(id), "r"(cnt) : "memory");
}
__device__ __forceinline__ void nbar_arrive(int id, int cnt) {
    asm volatile("bar.arrive %0, %1;" :: "r"(id), "r"(cnt) : "memory");
}

// ---------------- matvec for one half-batch (NP graph-pairs from p0) ----------------
template<int NP>
__device__ __forceinline__ void matvec_half(
    int p0, const float* __restrict__ hp, float* __restrict__ qst,
    float* __restrict__ out, float* creg, int f,
    float bi, float bf, float bg, float bo,
    int bid, int G, bool final_step)
{
    unsigned long long acc[4][NP];
    #pragma unroll
    for (int g = 0; g < 4; ++g)
        #pragma unroll
        for (int p = 0; p < NP; ++p) acc[g][p] = 0ull;

    for (int kc = 0; kc < 64; ++kc) {
        unsigned long long wp[4][4];
        #pragma unroll
        for (int g = 0; g < 4; ++g) {
            float4 wv = g_WcT4[kc * 1024 + 256 * g + f];
            wp[g][0] = pack2(wv.x, wv.x); wp[g][1] = pack2(wv.y, wv.y);
            wp[g][2] = pack2(wv.z, wv.z); wp[g][3] = pack2(wv.w, wv.w);
        }
        #pragma unroll
        for (int p = 0; p < NP; ++p) {
            ulonglong2 hA = *(const ulonglong2*)&hp[((p0 + p) * 256 + kc * 4) * 2];
            ulonglong2 hB = *(const ulonglong2*)&hp[((p0 + p) * 256 + kc * 4 + 2) * 2];
            #pragma unroll
            for (int g = 0; g < 4; ++g) {
                ffma2(acc[g][p], hA.x, wp[g][0]);
                ffma2(acc[g][p], hA.y, wp[g][1]);
                ffma2(acc[g][p], hB.x, wp[g][2]);
                ffma2(acc[g][p], hB.y, wp[g][3]);
            }
        }
    }
    #pragma unroll
    for (int p = 0; p < NP; ++p) {
        float2 iv = unpack2(acc[0][p]), fv = unpack2(acc[1][p]);
        float2 gv = unpack2(acc[2][p]), ov = unpack2(acc[3][p]);
        #pragma unroll
        for (int l = 0; l < 2; ++l) {
            int i = (p0 + p) * 2 + l;
            float gi = (l ? iv.y : iv.x) + bi;
            float gf = (l ? fv.y : fv.x) + bf;
            float gg = (l ? gv.y : gv.x) + bg;
            float go = (l ? ov.y : ov.x) + bo;
            float cold = creg[p * 2 + l];
            float cn = sigmoidf_(gf) * cold + sigmoidf_(gi) * tanhf(gg);
            float qn = sigmoidf_(go) * tanhf(cn);
            creg[p * 2 + l] = cn;
            qst[i * H + f] = qn;
            if (final_step && i < G)
                out[((size_t)bid + (size_t)GRID * i) * (2 * H) + f] = qn;
        }
    }
}

// ---------------- SMEM layout (floats) ----------------
// xs[2][16384] | hp[7][256]x2 | qst[14][256] | sc[64] | red[384]x2
#define SM_FLOATS (32768 + 3584 + 3584 + 64 + 768)
#define SM_BYTES  (SM_FLOATS * 4 + 16)

__global__ void __launch_bounds__(NTHR, 1)
fused_kernel(const float* __restrict__ x, float* __restrict__ out) {
    extern __shared__ __align__(16) unsigned char smraw[];
    float* xs  = (float*)smraw;                 // [2][16384]
    float* hp  = xs  + 2 * TILE_F;              // [7][256] float2 (graph pairs)
    float* qst = hp  + 3584;                    // [14][256]
    float* sc  = qst + GMAX * H;                // [64]
    float* red = sc  + 64;                      // [384] float2

    uint32_t smem_base;
    asm("{ .reg .u64 t; cvta.to.shared.u64 t, %1; cvt.u32.u64 %0, t; }"
        : "=r"(smem_base) : "l"(smraw));
    uint32_t mb0 = smem_base + SM_FLOATS * 4;
    uint32_t mb1 = mb0 + 8;

    int tid  = threadIdx.x;
    int bid  = blockIdx.x;
    int G    = (NG - bid + GRID - 1) / GRID;    // 13 or 14
    int total = 3 * G;

    // init shared state (all threads)
    for (int idx = tid; idx < 3584; idx += NTHR) hp[idx] = 0.0f;
    for (int idx = tid; idx < GMAX * H; idx += NTHR) qst[idx] = g_q0[idx & (H - 1)];
    if (tid == 0) {
        asm volatile("mbarrier.init.shared.b64 [%0], 1;" :: "r"(mb0) : "memory");
        asm volatile("mbarrier.init.shared.b64 [%0], 1;" :: "r"(mb1) : "memory");
    }
    __syncthreads();

    if (tid < ATT_THR) {
        // ================= ATTENTION warps (0-11) =================
        int lane = tid & 31;
        int w    = tid >> 5;

        auto issue = [&](int j) {
            if (j < total && tid == 0) {
                int i2 = j % G;
                size_t g = (size_t)bid + (size_t)GRID * i2;
                uint32_t mbj = (j & 1) ? mb1 : mb0;
                uint32_t dst = smem_base + (uint32_t)(j & 1) * TILE_B;
                asm volatile("mbarrier.arrive.expect_tx.shared.b64 _, [%0], %1;"
                             :: "r"(mbj), "r"(TILE_B) : "memory");
                asm volatile("cp.async.bulk.shared::cta.global.mbarrier::complete_tx::bytes "
                             "[%0], [%1], %2, [%3];"
                             :: "r"(dst), "l"(x + g * TILE_F), "r"(TILE_B), "r"(mbj)
                             : "memory");
            }
        };
        issue(0); issue(1);

        int ph0 = 0, ph1 = 0;
        int jj = 0;
        for (int s = 0; s < 3; ++s) {
            for (int half = 0; half < 2; ++half) {
                if (s > 0) nbar_sync(4 + half, NTHR);   // wait q(s,half) from mv
                int i0 = half ? 8 : 0;
                int i1 = half ? G : 8;
                for (int i = i0; i < i1; ++i, ++jj) {
                    int buf = jj & 1;
                    // wait tile
                    {
                        uint32_t mbc = buf ? mb1 : mb0;
                        int phc = buf ? ph1 : ph0;
                        uint32_t done;
                        do {
                            asm volatile(
                                "{ .reg .pred p; "
                                "mbarrier.try_wait.parity.acquire.cta.shared::cta.b64 p, [%1], %2, 0x989680; "
                                "selp.b32 %0, 1, 0, p; }"
                                : "=r"(done) : "r"(mbc), "r"(phc) : "memory");
                        } while (!done);
                        if (buf) ph1 ^= 1; else ph0 ^= 1;
                    }

                    const float* X    = xs + buf * TILE_F;
                    const float* qrow = qst + i * H;

                    // scores: warp w -> atoms w, w+12, w+24, ...
                    float4 q4a = *(const float4*)&qrow[4 * lane];
                    float4 q4b = *(const float4*)&qrow[128 + 4 * lane];
                    #pragma unroll
                    for (int k = 0; k < 6; ++k) {
                        int a = w + 12 * k;
                        if (a < APG) {
                            const float* row = X + a * H;
                            float4 xa = *(const float4*)&row[4 * lane];
                            float4 xb = *(const float4*)&row[128 + 4 * lane];
                            float p = xa.x*q4a.x + xa.y*q4a.y + xa.z*q4a.z + xa.w*q4a.w
                                    + xb.x*q4b.x + xb.y*q4b.y + xb.z*q4b.z + xb.w*q4b.w;
                            #pragma unroll
                            for (int off = 16; off; off >>= 1)
                                p += __shfl_xor_sync(0xffffffffu, p, off);
                            if (lane == 0) sc[a] = p;
                        }
                    }
                    nbar_sync(1, ATT_THR);

                    // softmax over 64 (warp 0)
                    if (w == 0) {
                        float v0 = sc[lane], v1 = sc[lane + 32];
                        float mx = fmaxf(v0, v1);
                        #pragma unroll
                        for (int off = 16; off; off >>= 1)
                            mx = fmaxf(mx, __shfl_xor_sync(0xffffffffu, mx, off));
                        float e0 = __expf(v0 - mx), e1 = __expf(v1 - mx);
                        float ssum = e0 + e1;
                        #pragma unroll
                        for (int off = 16; off; off >>= 1)
                            ssum += __shfl_xor_sync(0xffffffffu, ssum, off);
                        float inv = 1.0f / ssum;
                        sc[lane]      = e0 * inv;
                        sc[lane + 32] = e1 * inv;
                    }
                    nbar_sync(1, ATT_THR);

                    // weighted sum: 384 threads; feature-pair x third-of-atoms
                    {
                        int fp    = tid & 127;
                        int third = tid >> 7;            // 0,1,2
                        int a0    = third * 21;
                        int cnt   = (third == 2) ? 22 : 21;
                        float2 r2 = make_float2(0.0f, 0.0f);
                        const float* Xq = X + a0 * H + 2 * fp;
                        for (int a = 0; a < cnt; ++a) {
                            float sw = sc[a0 + a];
                            float2 xv = *(const float2*)&Xq[a * H];
                            r2.x = fmaf(sw, xv.x, r2.x);
                            r2.y = fmaf(sw, xv.y, r2.y);
                        }
                        *(float2*)&red[tid * 2] = r2;
                    }
                    nbar_sync(1, ATT_THR);   // X consumed

                    issue(jj + 2);           // refill this buffer

                    if (tid < 128) {
                        float2 r0 = *(const float2*)&red[tid * 2];
                        float2 r1 = *(const float2*)&red[(tid + 128) * 2];
                        float2 r2 = *(const float2*)&red[(tid + 256) * 2];
                        float2 rr = make_float2(r0.x + r1.x + r2.x,
                                                r0.y + r1.y + r2.y);
                        int p = i >> 1, l = i & 1;
                        hp[(p * 256 + 2 * tid)     * 2 + l] = rr.x;
                        hp[(p * 256 + 2 * tid + 1) * 2 + l] = rr.y;
                        if (s == 2) {
                            size_t g = (size_t)bid + (size_t)GRID * i;
                            *(float2*)&out[g * (2 * H) + H + 2 * tid] = rr;
                        }
                    }
                    // no trailing bar: next-tile bars order red/hp reuse;
                    // hp->mv handoff ordered by the arrive below.
                }
                if (s < 2) {
                    nbar_sync(1, ATT_THR);   // hp writes done across att warps
                    __threadfence_block();
                    nbar_arrive(2 + half, NTHR);   // r(s,half) ready
                }
            }
        }
    } else {
        // ================= MATVEC warps (12-19) =================
        int f = tid - ATT_THR;                  // 0..255 (feature)
        float bi = g_bc[f],       bf = g_bc[256 + f];
        float bg = g_bc[512 + f], bo = g_bc[768 + f];
        float creg[14];
        float c0 = g_c0[f];
        #pragma unroll
        for (int i = 0; i < 14; ++i) creg[i] = c0;

        for (int t = 1; t <= 2; ++t) {
            bool fin = (t == 2);
            // half A: pairs 0-3 (graphs 0-7)
            nbar_sync(2, NTHR);
            matvec_half<4>(0, hp, qst, out, &creg[0], f, bi, bf, bg, bo, bid, G, fin);
            __threadfence_block();
            nbar_arrive(4, NTHR);
            // half B: pairs 4-6 (graphs 8-13)
            nbar_sync(3, NTHR);
            matvec_half<3>(4, hp, qst, out, &creg[8], f, bi, bf, bg, bo, bid, G, fin);
            __threadfence_block();
            nbar_arrive(5, NTHR);
        }
    }
}

// ---------------- launch ----------------
extern "C" void kernel_launch(void* const* d_in, const int* in_sizes, int n_in,
                              void* d_out, int out_size) {
    const float* x    = (const float*)d_in[0];
    const float* W_ih = (const float*)d_in[3];
    const float* W_hh = (const float*)d_in[4];
    const float* b_ih = (const float*)d_in[5];
    const float* b_hh = (const float*)d_in[6];
    float* out = (float*)d_out;

    cudaFuncSetAttribute(fused_kernel,
                         cudaFuncAttributeMaxDynamicSharedMemorySize,
                         (int)SM_BYTES);

    prep_kernel<<<256, 256>>>(W_ih, W_hh, b_ih, b_hh);
    fused_kernel<<<GRID, NTHR, SM_BYTES>>>(x, out);
}

// round 8
// speedup vs baseline: 1.1298x; 1.1298x over previous
#include <cuda_runtime.h>
#include <cstdint>

#define H        256
#define NG       2048
#define APG      64
#define GRID     296          // 2 CTAs per SM
#define TILE_F   (APG*H)      // 16384 floats
#define TILE_B   (TILE_F*4)   // 65536 bytes
#define GMAXC    7            // max graphs per CTA (pairs padded to 4)

// ---------------- device globals ----------------
__device__ float4 g_WcT4[64 * 1024];   // [kc][n] = (W_ih+W_hh)[n][4kc..4kc+3]
__device__ float  g_bc[1024];
__device__ float  g_q0[H];
__device__ float  g_c0[H];

__device__ __forceinline__ float sigmoidf_(float v) {
    return 1.0f / (1.0f + __expf(-v));
}

// ---------------- prep ----------------
__global__ void prep_kernel(const float* __restrict__ W_ih,
                            const float* __restrict__ W_hh,
                            const float* __restrict__ b_ih,
                            const float* __restrict__ b_hh) {
    int idx = blockIdx.x * 256 + threadIdx.x;    // 65536 threads
    int kc = idx >> 10, n = idx & 1023;
    float4 a = *(const float4*)&W_ih[n * H + kc * 4];
    float4 b = *(const float4*)&W_hh[n * H + kc * 4];
    g_WcT4[idx] = make_float4(a.x + b.x, a.y + b.y, a.z + b.z, a.w + b.w);
    if (idx < 1024) g_bc[idx] = b_ih[idx] + b_hh[idx];
    if (idx < H) {
        float gi = b_ih[idx]       + b_hh[idx];
        float gg = b_ih[512 + idx] + b_hh[512 + idx];
        float go = b_ih[768 + idx] + b_hh[768 + idx];
        float c  = sigmoidf_(gi) * tanhf(gg);
        g_c0[idx] = c;
        g_q0[idx] = sigmoidf_(go) * tanhf(c);
    }
}

// ---------------- packed f32x2 helpers ----------------
__device__ __forceinline__ unsigned long long pack2(float lo, float hi) {
    unsigned long long r;
    asm("mov.b64 %0, {%1, %2};" : "=l"(r) : "f"(lo), "f"(hi));
    return r;
}
__device__ __forceinline__ void ffma2(unsigned long long& d,
                                      unsigned long long a,
                                      unsigned long long b) {
    asm("fma.rn.f32x2 %0, %1, %2, %0;" : "+l"(d) : "l"(a), "l"(b));
}
__device__ __forceinline__ float2 unpack2(unsigned long long v) {
    union { unsigned long long u; float2 f; } cv; cv.u = v; return cv.f;
}

// ---------------- SMEM layout (floats) ----------------
// xs[16384] | part[16][256] | hp[4][256]x2 | qst[8][256] | sc[64]
#define SM_FLOATS (16384 + 4096 + 2048 + 2048 + 64)
#define SM_BYTES  (SM_FLOATS * 4 + 8)

__global__ void __launch_bounds__(512, 2)
fused_kernel(const float* __restrict__ x, float* __restrict__ out) {
    extern __shared__ __align__(16) unsigned char smraw[];
    float* xs   = (float*)smraw;                // [64][256]
    float* part = xs   + TILE_F;                // [16][256]
    float* hp   = part + 4096;                  // [4][256]x2 (graph-pair packed r)
    float* qst  = hp   + 2048;                  // [8][256]
    float* sc   = qst  + 2048;                  // [64]

    uint32_t smem_base;
    asm("{ .reg .u64 t; cvta.to.shared.u64 t, %1; cvt.u32.u64 %0, t; }"
        : "=r"(smem_base) : "l"(smraw));
    uint32_t mbar = smem_base + SM_FLOATS * 4;

    int tid  = threadIdx.x;
    int lane = tid & 31;
    int w    = tid >> 5;
    int bid  = blockIdx.x;
    int G    = (NG - bid + GRID - 1) / GRID;    // 6 or 7
    int total = 3 * G;

    // init shared state
    for (int idx = tid; idx < 2048; idx += 512) hp[idx] = 0.0f;
    for (int idx = tid; idx < 2048; idx += 512) qst[idx] = g_q0[idx & (H - 1)];
    if (tid == 0)
        asm volatile("mbarrier.init.shared.b64 [%0], 1;" :: "r"(mbar) : "memory");
    __syncthreads();

    // matvec persistent thread state: feature f, pair-group
    int f  = tid & 255;
    int pb = (tid >> 8) * 2;       // pair base: 0 or 2 (graphs 4*pb/2..)
    float bi = g_bc[f],       bf = g_bc[256 + f];
    float bg = g_bc[512 + f], bo = g_bc[768 + f];
    float creg[4];
    {
        float c0 = g_c0[f];
        #pragma unroll
        for (int i = 0; i < 4; ++i) creg[i] = c0;
    }

    auto issue = [&](int j) {
        if (j < total && tid == 0) {
            int i2 = j % G;
            size_t g = (size_t)bid + (size_t)GRID * i2;
            asm volatile("mbarrier.arrive.expect_tx.shared.b64 _, [%0], %1;"
                         :: "r"(mbar), "r"(TILE_B) : "memory");
            asm volatile("cp.async.bulk.shared::cta.global.mbarrier::complete_tx::bytes "
                         "[%0], [%1], %2, [%3];"
                         :: "r"(smem_base), "l"(x + g * TILE_F), "r"(TILE_B), "r"(mbar)
                         : "memory");
        }
    };
    issue(0);

    int ph = 0;
    int jj = 0;
    for (int s = 0; s < 3; ++s) {
        // ================= mat-vec + LSTM pointwise (all 512 threads) =======
        if (s > 0) {
            unsigned long long acc[4][2];
            #pragma unroll
            for (int g = 0; g < 4; ++g) { acc[g][0] = 0ull; acc[g][1] = 0ull; }

            for (int kc = 0; kc < 64; ++kc) {
                unsigned long long wp[4][4];
                #pragma unroll
                for (int g = 0; g < 4; ++g) {
                    float4 wv = g_WcT4[kc * 1024 + 256 * g + f];
                    wp[g][0] = pack2(wv.x, wv.x); wp[g][1] = pack2(wv.y, wv.y);
                    wp[g][2] = pack2(wv.z, wv.z); wp[g][3] = pack2(wv.w, wv.w);
                }
                #pragma unroll
                for (int p = 0; p < 2; ++p) {
                    ulonglong2 hA = *(const ulonglong2*)&hp[((pb + p) * 256 + kc * 4) * 2];
                    ulonglong2 hB = *(const ulonglong2*)&hp[((pb + p) * 256 + kc * 4 + 2) * 2];
                    #pragma unroll
                    for (int g = 0; g < 4; ++g) {
                        ffma2(acc[g][p], hA.x, wp[g][0]);
                        ffma2(acc[g][p], hA.y, wp[g][1]);
                        ffma2(acc[g][p], hB.x, wp[g][2]);
                        ffma2(acc[g][p], hB.y, wp[g][3]);
                    }
                }
            }
            #pragma unroll
            for (int p = 0; p < 2; ++p) {
                float2 iv = unpack2(acc[0][p]), fv = unpack2(acc[1][p]);
                float2 gv = unpack2(acc[2][p]), ov = unpack2(acc[3][p]);
                #pragma unroll
                for (int l = 0; l < 2; ++l) {
                    int i = (pb + p) * 2 + l;
                    float gi = (l ? iv.y : iv.x) + bi;
                    float gf = (l ? fv.y : fv.x) + bf;
                    float gg = (l ? gv.y : gv.x) + bg;
                    float go = (l ? ov.y : ov.x) + bo;
                    float cold = creg[p * 2 + l];
                    float cn = sigmoidf_(gf) * cold + sigmoidf_(gi) * tanhf(gg);
                    float qn = sigmoidf_(go) * tanhf(cn);
                    creg[p * 2 + l] = cn;
                    qst[i * H + f] = qn;
                    if (s == 2 && i < G)
                        out[((size_t)bid + (size_t)GRID * i) * (2 * H) + f] = qn;
                }
            }
            __syncthreads();   // qst visible; hp free for rewrite
        }

        // ================= attention =================
        for (int i = 0; i < G; ++i, ++jj) {
            // wait for tile (all threads)
            {
                uint32_t done;
                do {
                    asm volatile(
                        "{ .reg .pred p; "
                        "mbarrier.try_wait.parity.acquire.cta.shared::cta.b64 p, [%1], %2, 0x989680; "
                        "selp.b32 %0, 1, 0, p; }"
                        : "=r"(done) : "r"(mbar), "r"(ph) : "memory");
                } while (!done);
                ph ^= 1;
            }

            const float* qrow = qst + i * H;

            // scores: warp w -> atoms 4w..4w+3; x kept in registers
            float4 q4a = *(const float4*)&qrow[4 * lane];
            float4 q4b = *(const float4*)&qrow[128 + 4 * lane];
            float4 xr[4][2];
            #pragma unroll
            for (int aa = 0; aa < 4; ++aa) {
                const float* row = xs + (w * 4 + aa) * H;
                xr[aa][0] = *(const float4*)&row[4 * lane];
                xr[aa][1] = *(const float4*)&row[128 + 4 * lane];
                float p = xr[aa][0].x*q4a.x + xr[aa][0].y*q4a.y
                        + xr[aa][0].z*q4a.z + xr[aa][0].w*q4a.w
                        + xr[aa][1].x*q4b.x + xr[aa][1].y*q4b.y
                        + xr[aa][1].z*q4b.z + xr[aa][1].w*q4b.w;
                #pragma unroll
                for (int off = 16; off; off >>= 1)
                    p += __shfl_xor_sync(0xffffffffu, p, off);
                if (lane == 0) sc[w * 4 + aa] = p;
            }
            __syncthreads();   // xs fully consumed; sc complete

            issue(jj + 1);     // refill the buffer NOW (overlaps the rest)

            // softmax over 64 (warp 0)
            if (w == 0) {
                float v0 = sc[lane], v1 = sc[lane + 32];
                float mx = fmaxf(v0, v1);
                #pragma unroll
                for (int off = 16; off; off >>= 1)
                    mx = fmaxf(mx, __shfl_xor_sync(0xffffffffu, mx, off));
                float e0 = __expf(v0 - mx), e1 = __expf(v1 - mx);
                float ssum = e0 + e1;
                #pragma unroll
                for (int off = 16; off; off >>= 1)
                    ssum += __shfl_xor_sync(0xffffffffu, ssum, off);
                float inv = 1.0f / ssum;
                sc[lane]      = e0 * inv;
                sc[lane + 32] = e1 * inv;
            }
            __syncthreads();

            // weighted sum from registers: per-warp partials
            {
                float a0 = sc[w * 4 + 0], a1 = sc[w * 4 + 1];
                float a2 = sc[w * 4 + 2], a3 = sc[w * 4 + 3];
                float4 p0, p1;
                p0.x = a0*xr[0][0].x + a1*xr[1][0].x + a2*xr[2][0].x + a3*xr[3][0].x;
                p0.y = a0*xr[0][0].y + a1*xr[1][0].y + a2*xr[2][0].y + a3*xr[3][0].y;
                p0.z = a0*xr[0][0].z + a1*xr[1][0].z + a2*xr[2][0].z + a3*xr[3][0].z;
                p0.w = a0*xr[0][0].w + a1*xr[1][0].w + a2*xr[2][0].w + a3*xr[3][0].w;
                p1.x = a0*xr[0][1].x + a1*xr[1][1].x + a2*xr[2][1].x + a3*xr[3][1].x;
                p1.y = a0*xr[0][1].y + a1*xr[1][1].y + a2*xr[2][1].y + a3*xr[3][1].y;
                p1.z = a0*xr[0][1].z + a1*xr[1][1].z + a2*xr[2][1].z + a3*xr[3][1].z;
                p1.w = a0*xr[0][1].w + a1*xr[1][1].w + a2*xr[2][1].w + a3*xr[3][1].w;
                *(float4*)&part[w * H + 4 * lane]       = p0;
                *(float4*)&part[w * H + 128 + 4 * lane] = p1;
            }
            __syncthreads();

            // reduce 16 partials -> r (threads 0..255)
            if (tid < H) {
                float rr = 0.0f;
                #pragma unroll
                for (int ww = 0; ww < 16; ++ww)
                    rr += part[ww * H + tid];
                int p = i >> 1, l = i & 1;
                hp[(p * 256 + tid) * 2 + l] = rr;
                if (s == 2)
                    out[((size_t)bid + (size_t)GRID * i) * (2 * H) + H + tid] = rr;
            }
            __syncthreads();   // part free for next tile; hp ordered for matvec
        }
    }
}

// ---------------- launch ----------------
extern "C" void kernel_launch(void* const* d_in, const int* in_sizes, int n_in,
                              void* d_out, int out_size) {
    const float* x    = (const float*)d_in[0];
    const float* W_ih = (const float*)d_in[3];
    const float* W_hh = (const float*)d_in[4];
    const float* b_ih = (const float*)d_in[5];
    const float* b_hh = (const float*)d_in[6];
    float* out = (float*)d_out;

    cudaFuncSetAttribute(fused_kernel,
                         cudaFuncAttributeMaxDynamicSharedMemorySize,
                         (int)SM_BYTES);

    prep_kernel<<<256, 256>>>(W_ih, W_hh, b_ih, b_hh);
    fused_kernel<<<GRID, 512, SM_BYTES>>>(x, out);
}